// round 10
// baseline (speedup 1.0000x reference)
#include <cuda_runtime.h>

// Custom_RoPE: x (32, 8192, 128) fp32, cos/sin (8192, 128) fp32.
// out = x*cos + rotate_half(x)*sin ; obs_max/min over last dim.
// d_out layout: out[H*T*D] | obs_max[H*T] | obs_min[H*T].
//
// R6: R2 structure (proven best: .cs loads+stores, 4 rows/warp at same t)
// with two deltas:
//  - __launch_bounds__(256,5): RF fits 5 blocks at 48 regs -> occ 62.5%
//    (R2's minBlocks=4 left it at 50%)
//  - h-fast warp ordering (h in low 3 bits of warp id): the 8 warps sharing
//    a t are launch-adjacent, so their identical cos/sin line fetches
//    coalesce in-flight at L2

#define RH 32
#define RT 8192
#define RD 128

__global__ __launch_bounds__(256, 5) void rope_kernel(
    const float* __restrict__ x,
    const float* __restrict__ cosp,
    const float* __restrict__ sinp,
    float* __restrict__ out,
    float* __restrict__ omax,
    float* __restrict__ omin)
{
    const unsigned FULL = 0xffffffffu;
    int w    = (blockIdx.x * blockDim.x + threadIdx.x) >> 5;  // [0, 8*T)
    int lane = threadIdx.x & 31;
    int ll   = lane & 15;          // lane within half-warp
    int half = lane >> 4;          // head offset 0 or 16

    int h = w & 7;                 // h-slot fastest: warps sharing t adjacent
    int t = w >> 3;

    size_t rowA = (size_t)(h     + half * 16) * RT + t;   // head h   / h+16
    size_t rowB = (size_t)(h + 8 + half * 16) * RT + t;   // head h+8 / h+24
    size_t xa = rowA * RD;
    size_t xb = rowB * RD;
    size_t cb = (size_t)t * RD;

    // ---- 8 front-batched 16B loads ----
    float4 xloA = __ldcs(reinterpret_cast<const float4*>(x + xa)      + ll);
    float4 xhiA = __ldcs(reinterpret_cast<const float4*>(x + xa + 64) + ll);
    float4 xloB = __ldcs(reinterpret_cast<const float4*>(x + xb)      + ll);
    float4 xhiB = __ldcs(reinterpret_cast<const float4*>(x + xb + 64) + ll);
    float4 clo  = *(reinterpret_cast<const float4*>(cosp + cb)      + ll);
    float4 chi  = *(reinterpret_cast<const float4*>(cosp + cb + 64) + ll);
    float4 slo  = *(reinterpret_cast<const float4*>(sinp + cb)      + ll);
    float4 shi  = *(reinterpret_cast<const float4*>(sinp + cb + 64) + ll);

    // ---- row A ----
    float4 oloA, ohiA;
    oloA.x = fmaf(-xhiA.x, slo.x, xloA.x * clo.x);
    oloA.y = fmaf(-xhiA.y, slo.y, xloA.y * clo.y);
    oloA.z = fmaf(-xhiA.z, slo.z, xloA.z * clo.z);
    oloA.w = fmaf(-xhiA.w, slo.w, xloA.w * clo.w);
    ohiA.x = fmaf( xloA.x, shi.x, xhiA.x * chi.x);
    ohiA.y = fmaf( xloA.y, shi.y, xhiA.y * chi.y);
    ohiA.z = fmaf( xloA.z, shi.z, xhiA.z * chi.z);
    ohiA.w = fmaf( xloA.w, shi.w, xhiA.w * chi.w);
    __stcs(reinterpret_cast<float4*>(out + xa)      + ll, oloA);
    __stcs(reinterpret_cast<float4*>(out + xa + 64) + ll, ohiA);

    // ---- row B ----
    float4 oloB, ohiB;
    oloB.x = fmaf(-xhiB.x, slo.x, xloB.x * clo.x);
    oloB.y = fmaf(-xhiB.y, slo.y, xloB.y * clo.y);
    oloB.z = fmaf(-xhiB.z, slo.z, xloB.z * clo.z);
    oloB.w = fmaf(-xhiB.w, slo.w, xloB.w * clo.w);
    ohiB.x = fmaf( xloB.x, shi.x, xhiB.x * chi.x);
    ohiB.y = fmaf( xloB.y, shi.y, xhiB.y * chi.y);
    ohiB.z = fmaf( xloB.z, shi.z, xhiB.z * chi.z);
    ohiB.w = fmaf( xloB.w, shi.w, xhiB.w * chi.w);
    __stcs(reinterpret_cast<float4*>(out + xb)      + ll, oloB);
    __stcs(reinterpret_cast<float4*>(out + xb + 64) + ll, ohiB);

    // ---- per-row max/min: butterflies over 16-lane halves ----
    float mxA = fmaxf(fmaxf(fmaxf(oloA.x, oloA.y), fmaxf(oloA.z, oloA.w)),
                      fmaxf(fmaxf(ohiA.x, ohiA.y), fmaxf(ohiA.z, ohiA.w)));
    float mnA = fminf(fminf(fminf(oloA.x, oloA.y), fminf(oloA.z, oloA.w)),
                      fminf(fminf(ohiA.x, ohiA.y), fminf(ohiA.z, ohiA.w)));
    float mxB = fmaxf(fmaxf(fmaxf(oloB.x, oloB.y), fmaxf(oloB.z, oloB.w)),
                      fmaxf(fmaxf(ohiB.x, ohiB.y), fmaxf(ohiB.z, ohiB.w)));
    float mnB = fminf(fminf(fminf(oloB.x, oloB.y), fminf(oloB.z, oloB.w)),
                      fminf(fminf(ohiB.x, ohiB.y), fminf(ohiB.z, ohiB.w)));
    #pragma unroll
    for (int off = 8; off > 0; off >>= 1) {
        mxA = fmaxf(mxA, __shfl_xor_sync(FULL, mxA, off));
        mnA = fminf(mnA, __shfl_xor_sync(FULL, mnA, off));
        mxB = fmaxf(mxB, __shfl_xor_sync(FULL, mxB, off));
        mnB = fminf(mnB, __shfl_xor_sync(FULL, mnB, off));
    }
    if (ll == 0) {
        omax[rowA] = mxA;
        omin[rowA] = mnA;
        omax[rowB] = mxB;
        omin[rowB] = mnB;
    }
}

extern "C" void kernel_launch(void* const* d_in, const int* in_sizes, int n_in,
                              void* d_out, int out_size)
{
    // inputs: 0=x, 1=scale_x (unused), 2=cos, 3=scale_cos (unused),
    //         4=sin, 5=scale_sin (unused)
    const float* x    = (const float*)d_in[0];
    const float* cosp = (const float*)d_in[2];
    const float* sinp = (const float*)d_in[4];

    float* out  = (float*)d_out;
    float* omax = out + (size_t)RH * RT * RD;
    float* omin = omax + (size_t)RH * RT;

    const int warps = (RH / 4) * RT;        // 65536 (4 rows per warp)
    const int warps_per_block = 8;          // 256 threads
    const int blocks = warps / warps_per_block;

    rope_kernel<<<blocks, warps_per_block * 32>>>(x, cosp, sinp, out, omax, omin);
}

// round 12
// speedup vs baseline: 1.0743x; 1.0743x over previous
#include <cuda_runtime.h>

// Custom_RoPE: x (32, 8192, 128) fp32, cos/sin (8192, 128) fp32.
// out = x*cos + rotate_half(x)*sin ; obs_max/min over last dim.
// d_out layout: out[H*T*D] | obs_max[H*T] | obs_min[H*T].
//
// FINAL (= R2 champion, best of 6 measured configs: 39.1us kernel,
// ~6.7 TB/s effective = 84% of HBM spec for this 1:1 R/W stream):
//  - one warp = FOUR rows sharing the same t: heads {h, h+8, h+16, h+24}
//  - lanes 0-15 -> heads {h, h+8}; lanes 16-31 -> heads {h+16, h+24}
//  - one cos/sin register load serves all 4 rows
//  - 8 front-batched LDG.128 per lane; zero-shuffle rotate (each lane holds
//    both halves of its row)
//  - __ldcs reads + __stcs writes (measured best store policy: .cs < .wt < .wb)
//  - t-major warp ordering (h-fast ordering measured worse: scatters the
//    x-read DRAM page stream)
//  - 16-lane butterflies reduce two rows at once in disjoint half-warps
// Falsified levers: cp.async deep queues (-18%), higher occupancy (neutral),
// .wb/.wt stores, h-fast ordering. This is the mixed-R/W HBM wall.

#define RH 32
#define RT 8192
#define RD 128

__global__ __launch_bounds__(256, 4) void rope_kernel(
    const float* __restrict__ x,
    const float* __restrict__ cosp,
    const float* __restrict__ sinp,
    float* __restrict__ out,
    float* __restrict__ omax,
    float* __restrict__ omin)
{
    const unsigned FULL = 0xffffffffu;
    int w    = (blockIdx.x * blockDim.x + threadIdx.x) >> 5;  // [0, 8*T)
    int lane = threadIdx.x & 31;
    int ll   = lane & 15;          // lane within half-warp
    int half = lane >> 4;          // head offset 0 or 16

    int t = w & (RT - 1);
    int h = w >> 13;               // [0, 8)

    size_t rowA = (size_t)(h     + half * 16) * RT + t;   // head h   / h+16
    size_t rowB = (size_t)(h + 8 + half * 16) * RT + t;   // head h+8 / h+24
    size_t xa = rowA * RD;
    size_t xb = rowB * RD;
    size_t cb = (size_t)t * RD;

    // ---- 8 front-batched 16B loads ----
    float4 xloA = __ldcs(reinterpret_cast<const float4*>(x + xa)      + ll);
    float4 xhiA = __ldcs(reinterpret_cast<const float4*>(x + xa + 64) + ll);
    float4 xloB = __ldcs(reinterpret_cast<const float4*>(x + xb)      + ll);
    float4 xhiB = __ldcs(reinterpret_cast<const float4*>(x + xb + 64) + ll);
    float4 clo  = *(reinterpret_cast<const float4*>(cosp + cb)      + ll);
    float4 chi  = *(reinterpret_cast<const float4*>(cosp + cb + 64) + ll);
    float4 slo  = *(reinterpret_cast<const float4*>(sinp + cb)      + ll);
    float4 shi  = *(reinterpret_cast<const float4*>(sinp + cb + 64) + ll);

    // ---- row A ----
    float4 oloA, ohiA;
    oloA.x = fmaf(-xhiA.x, slo.x, xloA.x * clo.x);
    oloA.y = fmaf(-xhiA.y, slo.y, xloA.y * clo.y);
    oloA.z = fmaf(-xhiA.z, slo.z, xloA.z * clo.z);
    oloA.w = fmaf(-xhiA.w, slo.w, xloA.w * clo.w);
    ohiA.x = fmaf( xloA.x, shi.x, xhiA.x * chi.x);
    ohiA.y = fmaf( xloA.y, shi.y, xhiA.y * chi.y);
    ohiA.z = fmaf( xloA.z, shi.z, xhiA.z * chi.z);
    ohiA.w = fmaf( xloA.w, shi.w, xhiA.w * chi.w);
    __stcs(reinterpret_cast<float4*>(out + xa)      + ll, oloA);
    __stcs(reinterpret_cast<float4*>(out + xa + 64) + ll, ohiA);

    // ---- row B ----
    float4 oloB, ohiB;
    oloB.x = fmaf(-xhiB.x, slo.x, xloB.x * clo.x);
    oloB.y = fmaf(-xhiB.y, slo.y, xloB.y * clo.y);
    oloB.z = fmaf(-xhiB.z, slo.z, xloB.z * clo.z);
    oloB.w = fmaf(-xhiB.w, slo.w, xloB.w * clo.w);
    ohiB.x = fmaf( xloB.x, shi.x, xhiB.x * chi.x);
    ohiB.y = fmaf( xloB.y, shi.y, xhiB.y * chi.y);
    ohiB.z = fmaf( xloB.z, shi.z, xhiB.z * chi.z);
    ohiB.w = fmaf( xloB.w, shi.w, xhiB.w * chi.w);
    __stcs(reinterpret_cast<float4*>(out + xb)      + ll, oloB);
    __stcs(reinterpret_cast<float4*>(out + xb + 64) + ll, ohiB);

    // ---- per-row max/min: butterflies over 16-lane halves ----
    float mxA = fmaxf(fmaxf(fmaxf(oloA.x, oloA.y), fmaxf(oloA.z, oloA.w)),
                      fmaxf(fmaxf(ohiA.x, ohiA.y), fmaxf(ohiA.z, ohiA.w)));
    float mnA = fminf(fminf(fminf(oloA.x, oloA.y), fminf(oloA.z, oloA.w)),
                      fminf(fminf(ohiA.x, ohiA.y), fminf(ohiA.z, ohiA.w)));
    float mxB = fmaxf(fmaxf(fmaxf(oloB.x, oloB.y), fmaxf(oloB.z, oloB.w)),
                      fmaxf(fmaxf(ohiB.x, ohiB.y), fmaxf(ohiB.z, ohiB.w)));
    float mnB = fminf(fminf(fminf(oloB.x, oloB.y), fminf(oloB.z, oloB.w)),
                      fminf(fminf(ohiB.x, ohiB.y), fminf(ohiB.z, ohiB.w)));
    #pragma unroll
    for (int off = 8; off > 0; off >>= 1) {
        mxA = fmaxf(mxA, __shfl_xor_sync(FULL, mxA, off));
        mnA = fminf(mnA, __shfl_xor_sync(FULL, mnA, off));
        mxB = fmaxf(mxB, __shfl_xor_sync(FULL, mxB, off));
        mnB = fminf(mnB, __shfl_xor_sync(FULL, mnB, off));
    }
    if (ll == 0) {
        omax[rowA] = mxA;
        omin[rowA] = mnA;
        omax[rowB] = mxB;
        omin[rowB] = mnB;
    }
}

extern "C" void kernel_launch(void* const* d_in, const int* in_sizes, int n_in,
                              void* d_out, int out_size)
{
    // inputs: 0=x, 1=scale_x (unused), 2=cos, 3=scale_cos (unused),
    //         4=sin, 5=scale_sin (unused)
    const float* x    = (const float*)d_in[0];
    const float* cosp = (const float*)d_in[2];
    const float* sinp = (const float*)d_in[4];

    float* out  = (float*)d_out;
    float* omax = out + (size_t)RH * RT * RD;
    float* omin = omax + (size_t)RH * RT;

    const int warps = (RH / 4) * RT;        // 65536 (4 rows per warp)
    const int warps_per_block = 8;          // 256 threads
    const int blocks = warps / warps_per_block;

    rope_kernel<<<blocks, warps_per_block * 32>>>(x, cosp, sinp, out, omax, omin);
}